// round 14
// baseline (speedup 1.0000x reference)
#include <cuda_runtime.h>
#include <cuda_bf16.h>
#include <cstdint>

// Problem constants
#define BATCH 2
#define SEQ   2048
#define DMODEL 4096
#define NHEADS 32
#define NKVH   8
#define HEADD  128
#define REP    4
#define NROWS  (BATCH*SEQ)   // 4096
#define KVD    (NKVH*HEADD)  // 1024
#define NQKV   (DMODEL + 2*KVD)  // 6144 fused output cols

typedef unsigned long long ull;

// ---------------- scratch (device globals: no runtime allocation) ----------------
__device__ float g_q[(size_t)NROWS * DMODEL];
__device__ float g_k[(size_t)NROWS * KVD];
__device__ float g_v[(size_t)NROWS * KVD];
__device__ float g_attn[(size_t)NROWS * DMODEL];

// bf16 2-way-split operand buffers (hi + lo)
__device__ __nv_bfloat16 s_xh[(size_t)NROWS * DMODEL],  s_xl[(size_t)NROWS * DMODEL];
__device__ __nv_bfloat16 s_ah[(size_t)NROWS * DMODEL],  s_al[(size_t)NROWS * DMODEL];
__device__ __nv_bfloat16 s_wqkvh[(size_t)NQKV * DMODEL], s_wqkvl[(size_t)NQKV * DMODEL];
__device__ __nv_bfloat16 s_woh[(size_t)DMODEL * DMODEL], s_wol[(size_t)DMODEL * DMODEL];

// ---------------- f32x2 packed helpers (flash kernel) ----------------
__device__ __forceinline__ ull pk2(float lo, float hi) {
    ull r; asm("mov.b64 %0, {%1,%2};" : "=l"(r) : "f"(lo), "f"(hi)); return r;
}
__device__ __forceinline__ void up2(ull v, float &lo, float &hi) {
    asm("mov.b64 {%0,%1}, %2;" : "=f"(lo), "=f"(hi) : "l"(v));
}
__device__ __forceinline__ ull f2fma(ull a, ull b, ull c) {
    ull d; asm("fma.rn.f32x2 %0, %1, %2, %3;" : "=l"(d) : "l"(a), "l"(b), "l"(c)); return d;
}
__device__ __forceinline__ ull f2mul(ull a, ull b) {
    ull d; asm("mul.rn.f32x2 %0, %1, %2;" : "=l"(d) : "l"(a), "l"(b)); return d;
}

// ---------------- mma helpers (legacy mma.sync: base sm_103 compatible) ----------
__device__ __forceinline__ uint32_t cvta_smem(const void* p) {
    uint32_t a;
    asm("{ .reg .u64 t; cvta.to.shared.u64 t, %1; cvt.u32.u64 %0, t; }" : "=r"(a) : "l"(p));
    return a;
}
__device__ __forceinline__ void cp16(uint32_t dst, const void* src) {
    asm volatile("cp.async.cg.shared.global [%0], [%1], 16;" :: "r"(dst), "l"(src));
}
__device__ __forceinline__ void ldsm4(uint32_t addr, uint32_t* r) {
    asm volatile("ldmatrix.sync.aligned.m8n8.x4.shared.b16 {%0,%1,%2,%3}, [%4];"
                 : "=r"(r[0]), "=r"(r[1]), "=r"(r[2]), "=r"(r[3]) : "r"(addr));
}
#define MMA_BF16(d, a, b0, b1)                                                  \
    asm volatile("mma.sync.aligned.m16n8k16.row.col.f32.bf16.bf16.f32 "         \
                 "{%0,%1,%2,%3},{%4,%5,%6,%7},{%8,%9},{%0,%1,%2,%3};"           \
                 : "+f"((d)[0]), "+f"((d)[1]), "+f"((d)[2]), "+f"((d)[3])       \
                 : "r"((a)[0]), "r"((a)[1]), "r"((a)[2]), "r"((a)[3]),          \
                   "r"(b0), "r"(b1))

// =================================================================================
// Split conversion kernels (fp32 -> bf16 hi + bf16 lo)
// =================================================================================
__global__ void convert_split2(const float* __restrict__ a,
                               __nv_bfloat16* __restrict__ h,
                               __nv_bfloat16* __restrict__ l, int n)
{
    int i = blockIdx.x * blockDim.x + threadIdx.x;
    if (i >= n) return;
    float v = a[i];
    __nv_bfloat16 hh = __float2bfloat16(v);
    float r1 = v - __bfloat162float(hh);
    h[i] = hh; l[i] = __float2bfloat16(r1);
}

// w[K][N] fp32  ->  T{h,l}[N][K] bf16  (caller offsets th/tl for packing)
__global__ void transpose_split2(const float* __restrict__ w,
                                 __nv_bfloat16* __restrict__ th,
                                 __nv_bfloat16* __restrict__ tl, int K, int N)
{
    __shared__ float tile[32][33];
    int n0 = blockIdx.x * 32, k0 = blockIdx.y * 32;
    int tx = threadIdx.x, ty = threadIdx.y;  // (32, 8)
#pragma unroll
    for (int i = 0; i < 32; i += 8)
        tile[ty + i][tx] = w[(size_t)(k0 + ty + i) * N + n0 + tx];
    __syncthreads();
#pragma unroll
    for (int i = 0; i < 32; i += 8) {
        float v = tile[tx][ty + i];
        size_t o = (size_t)(n0 + ty + i) * K + k0 + tx;
        __nv_bfloat16 hh = __float2bfloat16(v);
        float r1 = v - __bfloat162float(hh);
        th[o] = hh; tl[o] = __float2bfloat16(r1);
    }
}

// =================================================================================
// bf16 split-GEMM (3 products) via mma.sync.m16n8k16, fused multi-output epilogue.
// C = A[M,K] @ BT[N,K]^T.  CTA tile 256x128, BK=64, 256 threads (8 warps, 64x64).
// Double-buffered cp.async (221KB smem, 1 CTA/SM). Epilogue routes columns:
//   n0 < 4096 -> C0 (stride 4096), n0 < 5120 -> C1 (stride 1024), else C2 (1024).
// =================================================================================
#define ROW_B    144                     // bytes per smem row (64 bf16 + 16B pad)
#define TILE_A   (256 * ROW_B)           // 36864
#define TILE_BT  (128 * ROW_B)           // 18432
#define BUF_B    (2 * TILE_A + 2 * TILE_BT)  // 110592
#define GEMM_SMEM (2 * BUF_B)            // 221184

__global__ void __launch_bounds__(256, 1) gemm_bf16x3_fused(
    const __nv_bfloat16* __restrict__ Ah, const __nv_bfloat16* __restrict__ Al,
    const __nv_bfloat16* __restrict__ Bh, const __nv_bfloat16* __restrict__ Bl,
    float* __restrict__ C0, float* __restrict__ C1, float* __restrict__ C2,
    int K)
{
    extern __shared__ __align__(1024) char smem[];
    const uint32_t sb = cvta_smem(smem);
    const int t = threadIdx.x, warp = t >> 5, lane = t & 31;
    const int wm = (warp & 3) << 6, wn = (warp >> 2) << 6;
    const int m0 = blockIdx.y << 8, n0 = blockIdx.x << 7;

    const int S = K >> 6;   // BK = 64

    const int brow = t & 127;
    auto load_stage = [&](int s) {
        const uint32_t base = sb + (uint32_t)(s & 1) * BUF_B;
        const int k0 = s << 6;
        const __nv_bfloat16* pah = Ah + (size_t)(m0 + t) * K + k0;
        const __nv_bfloat16* pal = Al + (size_t)(m0 + t) * K + k0;
        const __nv_bfloat16* pb  = (t < 128 ? Bh : Bl) + (size_t)(n0 + brow) * K + k0;
        uint32_t da = base + (uint32_t)t * ROW_B;
        uint32_t db = base + 2 * TILE_A + (t >= 128 ? TILE_BT : 0) + (uint32_t)brow * ROW_B;
#pragma unroll
        for (int c = 0; c < 8; ++c) {
            cp16(da + c * 16,          (const char*)pah + c * 16);
            cp16(da + TILE_A + c * 16, (const char*)pal + c * 16);
            cp16(db + c * 16,          (const char*)pb  + c * 16);
        }
        asm volatile("cp.async.commit_group;");
    };

    float acc[4][8][4];
#pragma unroll
    for (int i = 0; i < 4; ++i)
#pragma unroll
        for (int j = 0; j < 8; ++j)
#pragma unroll
            for (int e = 0; e < 4; ++e) acc[i][j][e] = 0.0f;

    // ldmatrix per-lane address components (identical mapping to R12-validated)
    const int q  = lane >> 3, rr = lane & 7;
    const int arow_off = rr + ((q & 1) << 3);
    const int acol_off = (q >> 1) << 4;            // bytes
    const int brow_off = ((q >> 1) << 3) + rr;
    const int bcol_off = (q & 1) << 4;             // bytes

    load_stage(0);

    for (int s = 0; s < S; ++s) {
        if (s + 1 < S) {
            load_stage(s + 1);
            asm volatile("cp.async.wait_group 1;" ::: "memory");
        } else {
            asm volatile("cp.async.wait_group 0;" ::: "memory");
        }
        __syncthreads();

        const uint32_t bufb = sb + (uint32_t)(s & 1) * BUF_B;
        const uint32_t ta_h = bufb, ta_l = bufb + TILE_A;
        const uint32_t tb_h = bufb + 2 * TILE_A, tb_l = tb_h + TILE_BT;

#pragma unroll
        for (int ksub = 0; ksub < 4; ++ksub) {
            const int kb = ksub << 5;   // 16 bf16 = 32 bytes per ksub
            uint32_t bh[4][4], bl[4][4];
#pragma unroll
            for (int np = 0; np < 4; ++np) {
                uint32_t off = (uint32_t)(wn + (np << 4) + brow_off) * ROW_B + kb + bcol_off;
                ldsm4(tb_h + off, bh[np]);
                ldsm4(tb_l + off, bl[np]);
            }
#pragma unroll
            for (int ma = 0; ma < 4; ++ma) {
                uint32_t ah[4], al[4];
                uint32_t off = (uint32_t)(wm + (ma << 4) + arow_off) * ROW_B + kb + acol_off;
                ldsm4(ta_h + off, ah);
                ldsm4(ta_l + off, al);
#pragma unroll
                for (int na = 0; na < 8; ++na) {
                    const uint32_t* ph = &bh[na >> 1][(na & 1) << 1];
                    const uint32_t* pl = &bl[na >> 1][(na & 1) << 1];
                    float* d = acc[ma][na];
                    MMA_BF16(d, ah, ph[0], ph[1]);
                    MMA_BF16(d, ah, pl[0], pl[1]);
                    MMA_BF16(d, al, ph[0], ph[1]);
                }
            }
        }
        __syncthreads();
    }

    // ---- epilogue with CTA-uniform region routing ----
    float* base; int ldc, c0;
    if (n0 < DMODEL)            { base = C0; ldc = DMODEL; c0 = n0; }
    else if (n0 < DMODEL + KVD) { base = C1; ldc = KVD;    c0 = n0 - DMODEL; }
    else                        { base = C2; ldc = KVD;    c0 = n0 - DMODEL - KVD; }

    const int g = lane >> 2, tq = lane & 3;
#pragma unroll
    for (int ma = 0; ma < 4; ++ma) {
#pragma unroll
        for (int na = 0; na < 8; ++na) {
            const int row = m0 + wm + (ma << 4) + g;
            const int col = c0 + wn + (na << 3) + (tq << 1);
            float* d = acc[ma][na];
            *(float2*)(base + (size_t)row * ldc + col)       = make_float2(d[0], d[1]);
            *(float2*)(base + (size_t)(row + 8) * ldc + col) = make_float2(d[2], d[3]);
        }
    }
}

// =================================================================================
// RoPE (unchanged)
// =================================================================================
template <int NH>
__global__ void rope_kernel(float* __restrict__ buf,
                            const float* __restrict__ ct,
                            const float* __restrict__ st, int total)
{
    int idx = blockIdx.x * blockDim.x + threadIdx.x;
    if (idx >= total) return;
    int p   = idx & 63;
    int h   = (idx >> 6) & (NH - 1);
    int row = idx / (64 * NH);
    int l   = row & (SEQ - 1);
    float c = ct[(l << 6) + p];
    float s = st[(l << 6) + p];
    float2* ptr = (float2*)(buf + ((size_t)row * NH + h) * HEADD + (p << 1));
    float2 v = *ptr;
    *ptr = make_float2(v.x * c - v.y * s, v.x * s + v.y * c);
}

// =================================================================================
// Flash attention (unchanged from R5/R12 pass)
// =================================================================================
#define FA_BM 64
#define FA_BN 64
#define QK_STRIDE 68
#define PS_STRIDE 65
#define FA_SMEM_FLOATS (2 * 128 * QK_STRIDE + FA_BN * 128 + FA_BM * PS_STRIDE)
#define FA_SMEM_BYTES  (FA_SMEM_FLOATS * 4)

__global__ void __launch_bounds__(256) flash_kernel(
    const float* __restrict__ q, const float* __restrict__ k,
    const float* __restrict__ v, float* __restrict__ out)
{
    extern __shared__ __align__(16) float sm[];
    float* Qt = sm;
    float* Kt = Qt + 128 * QK_STRIDE;
    float* Vs = Kt + 128 * QK_STRIDE;
    float* Ps = Vs + FA_BN * 128;

    const int qb = blockIdx.x, h = blockIdx.y, b = blockIdx.z;
    const int kvh = h >> 2;
    const int t  = threadIdx.x;
    const int tx = t & 15, ty = t >> 4;
    const int ty4 = ty << 2, tx4 = tx << 2, tx8 = tx << 3;
    const float scale = 0.08838834764831845f;

    const float* qbase = q + ((size_t)(b * SEQ + qb * FA_BM)) * DMODEL + h * HEADD;
    for (int i = t; i < FA_BM * 128; i += 256) {
        int r = i >> 7, d = i & 127;
        Qt[d * QK_STRIDE + r] = qbase[(size_t)r * DMODEL + d] * scale;
    }

    float m_i[4], l_i[4];
    ull  o2[4][4];
#pragma unroll
    for (int i = 0; i < 4; ++i) {
        m_i[i] = -1e30f; l_i[i] = 0.0f;
#pragma unroll
        for (int j = 0; j < 4; ++j) o2[i][j] = 0ull;
    }

    for (int kb = 0; kb <= qb; ++kb) {
        __syncthreads();
        const float* kbase = k + ((size_t)(b * SEQ + kb * FA_BN)) * KVD + kvh * HEADD;
        const float* vbase = v + ((size_t)(b * SEQ + kb * FA_BN)) * KVD + kvh * HEADD;
        for (int i = t; i < FA_BN * 128; i += 256) {
            int r = i >> 7, d = i & 127;
            Kt[d * QK_STRIDE + r] = kbase[(size_t)r * KVD + d];
        }
        for (int i = t; i < FA_BN * 128 / 4; i += 256) {
            int r = i >> 5, c4 = (i & 31) << 2;
            *(float4*)&Vs[r * 128 + c4] = *(const float4*)&vbase[(size_t)r * KVD + c4];
        }
        __syncthreads();

        ull s2[4][2] = {{0ull,0ull},{0ull,0ull},{0ull,0ull},{0ull,0ull}};
#pragma unroll 8
        for (int d = 0; d < 128; ++d) {
            const float* kr = &Kt[d * QK_STRIDE];
            ull b01 = *(const ull*)(kr + tx4);
            ull b23 = *(const ull*)(kr + tx4 + 2);
            float4 a = *(const float4*)&Qt[d * QK_STRIDE + ty4];
            float avv[4] = {a.x, a.y, a.z, a.w};
#pragma unroll
            for (int i = 0; i < 4; ++i) {
                ull aa = pk2(avv[i], avv[i]);
                s2[i][0] = f2fma(aa, b01, s2[i][0]);
                s2[i][1] = f2fma(aa, b23, s2[i][1]);
            }
        }
        float s[4][4];
#pragma unroll
        for (int i = 0; i < 4; ++i) {
            up2(s2[i][0], s[i][0], s[i][1]);
            up2(s2[i][1], s[i][2], s[i][3]);
        }

        if (kb == qb) {
#pragma unroll
            for (int i = 0; i < 4; ++i)
#pragma unroll
                for (int j = 0; j < 4; ++j)
                    if (tx4 + j > ty4 + i) s[i][j] = -1e30f;
        }

        float p[4][4], rsum[4], alpha[4];
#pragma unroll
        for (int i = 0; i < 4; ++i) {
            float mx = fmaxf(fmaxf(s[i][0], s[i][1]), fmaxf(s[i][2], s[i][3]));
#pragma unroll
            for (int off = 8; off >= 1; off >>= 1)
                mx = fmaxf(mx, __shfl_xor_sync(0xffffffffu, mx, off));
            float mn = fmaxf(m_i[i], mx);
            alpha[i] = __expf(m_i[i] - mn);
            m_i[i] = mn;
            float rs = 0.0f;
#pragma unroll
            for (int j = 0; j < 4; ++j) {
                p[i][j] = __expf(s[i][j] - mn);
                rs += p[i][j];
            }
#pragma unroll
            for (int off = 8; off >= 1; off >>= 1)
                rs += __shfl_xor_sync(0xffffffffu, rs, off);
            rsum[i] = rs;
        }
#pragma unroll
        for (int i = 0; i < 4; ++i) {
            l_i[i] = l_i[i] * alpha[i] + rsum[i];
            ull al2 = pk2(alpha[i], alpha[i]);
#pragma unroll
            for (int j = 0; j < 4; ++j) o2[i][j] = f2mul(o2[i][j], al2);
#pragma unroll
            for (int j = 0; j < 4; ++j) Ps[(ty4 + i) * PS_STRIDE + tx4 + j] = p[i][j];
        }
        __syncthreads();

#pragma unroll 4
        for (int j = 0; j < FA_BN; ++j) {
            const float* vr = &Vs[j * 128 + tx8];
            ull v0 = *(const ull*)(vr + 0);
            ull v1 = *(const ull*)(vr + 2);
            ull v2 = *(const ull*)(vr + 4);
            ull v3 = *(const ull*)(vr + 6);
#pragma unroll
            for (int i = 0; i < 4; ++i) {
                float pv = Ps[(ty4 + i) * PS_STRIDE + j];
                ull p2 = pk2(pv, pv);
                o2[i][0] = f2fma(p2, v0, o2[i][0]);
                o2[i][1] = f2fma(p2, v1, o2[i][1]);
                o2[i][2] = f2fma(p2, v2, o2[i][2]);
                o2[i][3] = f2fma(p2, v3, o2[i][3]);
            }
        }
    }

#pragma unroll
    for (int i = 0; i < 4; ++i) {
        float inv = 1.0f / l_i[i];
        float o[8];
        up2(o2[i][0], o[0], o[1]); up2(o2[i][1], o[2], o[3]);
        up2(o2[i][2], o[4], o[5]); up2(o2[i][3], o[6], o[7]);
#pragma unroll
        for (int jj = 0; jj < 8; ++jj) o[jj] *= inv;
        size_t row = (size_t)(b * SEQ + qb * FA_BM + ty4 + i);
        float* op = out + row * DMODEL + h * HEADD + tx8;
        *(float4*)(op + 0) = make_float4(o[0], o[1], o[2], o[3]);
        *(float4*)(op + 4) = make_float4(o[4], o[5], o[6], o[7]);
    }
}

// =================================================================================
// Host launcher
// =================================================================================
extern "C" void kernel_launch(void* const* d_in, const int* in_sizes, int n_in,
                              void* d_out, int out_size)
{
    const float* x    = (const float*)d_in[0];
    const float* wq   = (const float*)d_in[1];
    const float* wk   = (const float*)d_in[2];
    const float* wv   = (const float*)d_in[3];
    const float* wo   = (const float*)d_in[4];
    const float* fcos = (const float*)d_in[5];
    const float* fsin = (const float*)d_in[6];
    float* outp = (float*)d_out;

    float *gq, *gk, *gv, *ga;
    cudaGetSymbolAddress((void**)&gq, g_q);
    cudaGetSymbolAddress((void**)&gk, g_k);
    cudaGetSymbolAddress((void**)&gv, g_v);
    cudaGetSymbolAddress((void**)&ga, g_attn);

    __nv_bfloat16 *xh, *xl, *ah, *al, *wqkvh, *wqkvl, *woh, *wol;
    cudaGetSymbolAddress((void**)&xh, s_xh);       cudaGetSymbolAddress((void**)&xl, s_xl);
    cudaGetSymbolAddress((void**)&ah, s_ah);       cudaGetSymbolAddress((void**)&al, s_al);
    cudaGetSymbolAddress((void**)&wqkvh, s_wqkvh); cudaGetSymbolAddress((void**)&wqkvl, s_wqkvl);
    cudaGetSymbolAddress((void**)&woh, s_woh);     cudaGetSymbolAddress((void**)&wol, s_wol);

    cudaFuncSetAttribute(flash_kernel,
                         cudaFuncAttributeMaxDynamicSharedMemorySize, FA_SMEM_BYTES);
    cudaFuncSetAttribute(gemm_bf16x3_fused,
                         cudaFuncAttributeMaxDynamicSharedMemorySize, GEMM_SMEM);

    // ---- operand conversions (weights packed [q | k | v] along N) ----
    {
        int n = NROWS * DMODEL;
        convert_split2<<<(n + 255) / 256, 256>>>(x, xh, xl, n);
    }
    transpose_split2<<<dim3(DMODEL / 32, DMODEL / 32), dim3(32, 8)>>>(
        wq, wqkvh, wqkvl, DMODEL, DMODEL);
    transpose_split2<<<dim3(KVD / 32, DMODEL / 32), dim3(32, 8)>>>(
        wk, wqkvh + (size_t)DMODEL * DMODEL, wqkvl + (size_t)DMODEL * DMODEL, DMODEL, KVD);
    transpose_split2<<<dim3(KVD / 32, DMODEL / 32), dim3(32, 8)>>>(
        wv, wqkvh + (size_t)(DMODEL + KVD) * DMODEL, wqkvl + (size_t)(DMODEL + KVD) * DMODEL,
        DMODEL, KVD);
    transpose_split2<<<dim3(DMODEL / 32, DMODEL / 32), dim3(32, 8)>>>(
        wo, woh, wol, DMODEL, DMODEL);

    // ---- Fused QKV projection: one GEMM, N = 6144 ----
    gemm_bf16x3_fused<<<dim3(NQKV / 128, NROWS / 256), 256, GEMM_SMEM>>>(
        xh, xl, wqkvh, wqkvl, gq, gk, gv, DMODEL);

    // ---- RoPE ----
    {
        int totq = NROWS * NHEADS * 64;
        int totk = NROWS * NKVH * 64;
        rope_kernel<NHEADS><<<(totq + 255) / 256, 256>>>(gq, fcos, fsin, totq);
        rope_kernel<NKVH><<<(totk + 255) / 256, 256>>>(gk, fcos, fsin, totk);
    }

    // ---- Flash attention ----
    flash_kernel<<<dim3(SEQ / FA_BM, NHEADS, BATCH), 256, FA_SMEM_BYTES>>>(gq, gk, gv, ga);

    // ---- O projection (same kernel; N=4096 stays in region 0) ----
    {
        int n = NROWS * DMODEL;
        convert_split2<<<(n + 255) / 256, 256>>>(ga, ah, al, n);
    }
    gemm_bf16x3_fused<<<dim3(DMODEL / 128, NROWS / 256), 256, GEMM_SMEM>>>(
        ah, al, woh, wol, outp, outp, outp, DMODEL);
}

// round 15
// speedup vs baseline: 1.6327x; 1.6327x over previous
#include <cuda_runtime.h>
#include <cuda_bf16.h>
#include <cstdint>

// Problem constants
#define BATCH 2
#define SEQ   2048
#define DMODEL 4096
#define NHEADS 32
#define NKVH   8
#define HEADD  128
#define REP    4
#define NROWS  (BATCH*SEQ)   // 4096
#define KVD    (NKVH*HEADD)  // 1024
#define NQKV   (DMODEL + 2*KVD)  // 6144

typedef unsigned long long ull;

// ---------------- scratch (device globals: no runtime allocation) ----------------
__device__ float g_q[(size_t)NROWS * DMODEL];
__device__ float g_k[(size_t)NROWS * KVD];
__device__ float g_v[(size_t)NROWS * KVD];

// bf16 2-way-split operand buffers (hi + lo)
__device__ __nv_bfloat16 s_xh[(size_t)NROWS * DMODEL],  s_xl[(size_t)NROWS * DMODEL];
__device__ __nv_bfloat16 s_ah[(size_t)NROWS * DMODEL],  s_al[(size_t)NROWS * DMODEL];
__device__ __nv_bfloat16 s_wqkvh[(size_t)NQKV * DMODEL], s_wqkvl[(size_t)NQKV * DMODEL];
__device__ __nv_bfloat16 s_woh[(size_t)DMODEL * DMODEL], s_wol[(size_t)DMODEL * DMODEL];

// ---------------- f32x2 packed helpers (flash kernel) ----------------
__device__ __forceinline__ ull pk2(float lo, float hi) {
    ull r; asm("mov.b64 %0, {%1,%2};" : "=l"(r) : "f"(lo), "f"(hi)); return r;
}
__device__ __forceinline__ void up2(ull v, float &lo, float &hi) {
    asm("mov.b64 {%0,%1}, %2;" : "=f"(lo), "=f"(hi) : "l"(v));
}
__device__ __forceinline__ ull f2fma(ull a, ull b, ull c) {
    ull d; asm("fma.rn.f32x2 %0, %1, %2, %3;" : "=l"(d) : "l"(a), "l"(b), "l"(c)); return d;
}
__device__ __forceinline__ ull f2mul(ull a, ull b) {
    ull d; asm("mul.rn.f32x2 %0, %1, %2;" : "=l"(d) : "l"(a), "l"(b)); return d;
}

// ---------------- mma helpers (legacy mma.sync: base sm_103 compatible) ----------
__device__ __forceinline__ uint32_t cvta_smem(const void* p) {
    uint32_t a;
    asm("{ .reg .u64 t; cvta.to.shared.u64 t, %1; cvt.u32.u64 %0, t; }" : "=r"(a) : "l"(p));
    return a;
}
__device__ __forceinline__ void cp16(uint32_t dst, const void* src) {
    asm volatile("cp.async.cg.shared.global [%0], [%1], 16;" :: "r"(dst), "l"(src));
}
__device__ __forceinline__ void ldsm4(uint32_t addr, uint32_t* r) {
    asm volatile("ldmatrix.sync.aligned.m8n8.x4.shared.b16 {%0,%1,%2,%3}, [%4];"
                 : "=r"(r[0]), "=r"(r[1]), "=r"(r[2]), "=r"(r[3]) : "r"(addr));
}
#define MMA_BF16(d, a, b0, b1)                                                  \
    asm volatile("mma.sync.aligned.m16n8k16.row.col.f32.bf16.bf16.f32 "         \
                 "{%0,%1,%2,%3},{%4,%5,%6,%7},{%8,%9},{%0,%1,%2,%3};"           \
                 : "+f"((d)[0]), "+f"((d)[1]), "+f"((d)[2]), "+f"((d)[3])       \
                 : "r"((a)[0]), "r"((a)[1]), "r"((a)[2]), "r"((a)[3]),          \
                   "r"(b0), "r"(b1))

// =================================================================================
// Split conversion kernels (fp32 -> bf16 hi + bf16 lo)
// =================================================================================
__global__ void convert_split2(const float* __restrict__ a,
                               __nv_bfloat16* __restrict__ h,
                               __nv_bfloat16* __restrict__ l, int n)
{
    int i = blockIdx.x * blockDim.x + threadIdx.x;
    if (i >= n) return;
    float v = a[i];
    __nv_bfloat16 hh = __float2bfloat16(v);
    float r1 = v - __bfloat162float(hh);
    h[i] = hh; l[i] = __float2bfloat16(r1);
}

// w[K][N] fp32  ->  T{h,l}[N][K] bf16  (caller offsets th/tl for packing)
__global__ void transpose_split2(const float* __restrict__ w,
                                 __nv_bfloat16* __restrict__ th,
                                 __nv_bfloat16* __restrict__ tl, int K, int N)
{
    __shared__ float tile[32][33];
    int n0 = blockIdx.x * 32, k0 = blockIdx.y * 32;
    int tx = threadIdx.x, ty = threadIdx.y;  // (32, 8)
#pragma unroll
    for (int i = 0; i < 32; i += 8)
        tile[ty + i][tx] = w[(size_t)(k0 + ty + i) * N + n0 + tx];
    __syncthreads();
#pragma unroll
    for (int i = 0; i < 32; i += 8) {
        float v = tile[tx][ty + i];
        size_t o = (size_t)(n0 + ty + i) * K + k0 + tx;
        __nv_bfloat16 hh = __float2bfloat16(v);
        float r1 = v - __bfloat162float(hh);
        th[o] = hh; tl[o] = __float2bfloat16(r1);
    }
}

// =================================================================================
// bf16 split-GEMM (3 products) via mma.sync.m16n8k16 — EXACT R12 tile config
// (128x128 CTA, BK=32, 128 threads, 2 CTAs/SM) + fused multi-region epilogue with
// optional in-register RoPE (rope pairs == the epilogue's float2 stores).
//   n0 < 4096 -> C0 (ld 4096, rope), n0 < 5120 -> C1 (ld 1024, rope), else C2 (1024).
// =================================================================================
#define ROW_B   80                       // bytes per smem tile row (32 bf16 + pad)
#define TILE_B  (128 * ROW_B)            // 10240 B
#define BUF_B   (4 * TILE_B)             // Ah Al Bh Bl = 40960 B
#define GEMM_SMEM (2 * BUF_B)            // 81920 B

__global__ void __launch_bounds__(128, 2) gemm_bf16x3_fused(
    const __nv_bfloat16* __restrict__ Ah, const __nv_bfloat16* __restrict__ Al,
    const __nv_bfloat16* __restrict__ Bh, const __nv_bfloat16* __restrict__ Bl,
    float* __restrict__ C0, float* __restrict__ C1, float* __restrict__ C2,
    const float* __restrict__ fcos, const float* __restrict__ fsin,
    int K, int rope_en)
{
    extern __shared__ __align__(16) char smem[];
    const uint32_t sb = cvta_smem(smem);
    const int t = threadIdx.x, warp = t >> 5, lane = t & 31;
    const int wm = (warp & 1) << 6, wn = (warp >> 1) << 6;
    const int m0 = blockIdx.y << 7, n0 = blockIdx.x << 7;

    const int S = K >> 5;   // BK = 32

    auto load_stage = [&](int s) {
        const uint32_t base = sb + (uint32_t)(s & 1) * BUF_B;
        const int k0 = s << 5;
        const __nv_bfloat16* srcs[4] = {
            Ah + (size_t)(m0 + t) * K + k0,
            Al + (size_t)(m0 + t) * K + k0,
            Bh + (size_t)(n0 + t) * K + k0,
            Bl + (size_t)(n0 + t) * K + k0
        };
#pragma unroll
        for (int ti = 0; ti < 4; ++ti) {
            uint32_t rowb = base + ti * TILE_B + (uint32_t)t * ROW_B;
#pragma unroll
            for (int c = 0; c < 4; ++c)
                cp16(rowb + c * 16, (const char*)srcs[ti] + c * 16);
        }
        asm volatile("cp.async.commit_group;");
    };

    float acc[4][8][4];
#pragma unroll
    for (int i = 0; i < 4; ++i)
#pragma unroll
        for (int j = 0; j < 8; ++j)
#pragma unroll
            for (int e = 0; e < 4; ++e) acc[i][j][e] = 0.0f;

    // ldmatrix per-lane address components (R12-validated)
    const int q  = lane >> 3, rr = lane & 7;
    const int arow_off = rr + ((q & 1) << 3);
    const int acol_off = (q >> 1) << 4;            // bytes
    const int brow_off = ((q >> 1) << 3) + rr;
    const int bcol_off = (q & 1) << 4;             // bytes

    load_stage(0);

    for (int s = 0; s < S; ++s) {
        if (s + 1 < S) {
            load_stage(s + 1);
            asm volatile("cp.async.wait_group 1;" ::: "memory");
        } else {
            asm volatile("cp.async.wait_group 0;" ::: "memory");
        }
        __syncthreads();

        const uint32_t bufb = sb + (uint32_t)(s & 1) * BUF_B;
        const uint32_t ta_h = bufb, ta_l = bufb + TILE_B;
        const uint32_t tb_h = bufb + 2 * TILE_B, tb_l = bufb + 3 * TILE_B;

#pragma unroll
        for (int ksub = 0; ksub < 2; ++ksub) {
            const int kb = ksub << 5;   // byte offset within row
            uint32_t bh[4][4], bl[4][4];
#pragma unroll
            for (int np = 0; np < 4; ++np) {
                uint32_t off = (uint32_t)(wn + (np << 4) + brow_off) * ROW_B + kb + bcol_off;
                ldsm4(tb_h + off, bh[np]);
                ldsm4(tb_l + off, bl[np]);
            }
#pragma unroll
            for (int ma = 0; ma < 4; ++ma) {
                uint32_t ah[4], al[4];
                uint32_t off = (uint32_t)(wm + (ma << 4) + arow_off) * ROW_B + kb + acol_off;
                ldsm4(ta_h + off, ah);
                ldsm4(ta_l + off, al);
#pragma unroll
                for (int na = 0; na < 8; ++na) {
                    const uint32_t* ph = &bh[na >> 1][(na & 1) << 1];
                    const uint32_t* pl = &bl[na >> 1][(na & 1) << 1];
                    float* d = acc[ma][na];
                    MMA_BF16(d, ah, ph[0], ph[1]);
                    MMA_BF16(d, ah, pl[0], pl[1]);
                    MMA_BF16(d, al, ph[0], ph[1]);
                }
            }
        }
        __syncthreads();
    }

    // ---- epilogue: region routing + optional fused RoPE ----
    float* base; int ldc, c0; int do_rope = 0;
    if (n0 < DMODEL)            { base = C0; ldc = DMODEL; c0 = n0; do_rope = rope_en; }
    else if (n0 < DMODEL + KVD) { base = C1; ldc = KVD;    c0 = n0 - DMODEL; do_rope = rope_en; }
    else                        { base = C2; ldc = KVD;    c0 = n0 - DMODEL - KVD; }

    const int g = lane >> 2, tq = lane & 3;
#pragma unroll
    for (int ma = 0; ma < 4; ++ma) {
#pragma unroll
        for (int na = 0; na < 8; ++na) {
            const int row = m0 + wm + (ma << 4) + g;
            const int col = c0 + wn + (na << 3) + (tq << 1);
            float* d = acc[ma][na];
            float2 v0 = make_float2(d[0], d[1]);
            float2 v1 = make_float2(d[2], d[3]);
            if (do_rope) {
                const int p  = (col & 127) >> 1;
                const int l0 = row & (SEQ - 1);
                const int l1 = (row + 8) & (SEQ - 1);
                float c0r = fcos[(l0 << 6) + p], s0r = fsin[(l0 << 6) + p];
                float c1r = fcos[(l1 << 6) + p], s1r = fsin[(l1 << 6) + p];
                v0 = make_float2(v0.x * c0r - v0.y * s0r, v0.x * s0r + v0.y * c0r);
                v1 = make_float2(v1.x * c1r - v1.y * s1r, v1.x * s1r + v1.y * c1r);
            }
            *(float2*)(base + (size_t)row * ldc + col)       = v0;
            *(float2*)(base + (size_t)(row + 8) * ldc + col) = v1;
        }
    }
}

// =================================================================================
// Flash attention (R5/R12-proven core) — epilogue now writes bf16 hi/lo split
// directly (feeds O-projection GEMM; fp32 g_attn + convert pass eliminated).
// =================================================================================
#define FA_BM 64
#define FA_BN 64
#define QK_STRIDE 68
#define PS_STRIDE 65
#define FA_SMEM_FLOATS (2 * 128 * QK_STRIDE + FA_BN * 128 + FA_BM * PS_STRIDE)
#define FA_SMEM_BYTES  (FA_SMEM_FLOATS * 4)

__global__ void __launch_bounds__(256) flash_kernel(
    const float* __restrict__ q, const float* __restrict__ k,
    const float* __restrict__ v,
    __nv_bfloat16* __restrict__ oh, __nv_bfloat16* __restrict__ ol)
{
    extern __shared__ __align__(16) float sm[];
    float* Qt = sm;
    float* Kt = Qt + 128 * QK_STRIDE;
    float* Vs = Kt + 128 * QK_STRIDE;
    float* Ps = Vs + FA_BN * 128;

    const int qb = blockIdx.x, h = blockIdx.y, b = blockIdx.z;
    const int kvh = h >> 2;
    const int t  = threadIdx.x;
    const int tx = t & 15, ty = t >> 4;
    const int ty4 = ty << 2, tx4 = tx << 2, tx8 = tx << 3;
    const float scale = 0.08838834764831845f;

    const float* qbase = q + ((size_t)(b * SEQ + qb * FA_BM)) * DMODEL + h * HEADD;
    for (int i = t; i < FA_BM * 128; i += 256) {
        int r = i >> 7, d = i & 127;
        Qt[d * QK_STRIDE + r] = qbase[(size_t)r * DMODEL + d] * scale;
    }

    float m_i[4], l_i[4];
    ull  o2[4][4];
#pragma unroll
    for (int i = 0; i < 4; ++i) {
        m_i[i] = -1e30f; l_i[i] = 0.0f;
#pragma unroll
        for (int j = 0; j < 4; ++j) o2[i][j] = 0ull;
    }

    for (int kb = 0; kb <= qb; ++kb) {
        __syncthreads();
        const float* kbase = k + ((size_t)(b * SEQ + kb * FA_BN)) * KVD + kvh * HEADD;
        const float* vbase = v + ((size_t)(b * SEQ + kb * FA_BN)) * KVD + kvh * HEADD;
        for (int i = t; i < FA_BN * 128; i += 256) {
            int r = i >> 7, d = i & 127;
            Kt[d * QK_STRIDE + r] = kbase[(size_t)r * KVD + d];
        }
        for (int i = t; i < FA_BN * 128 / 4; i += 256) {
            int r = i >> 5, c4 = (i & 31) << 2;
            *(float4*)&Vs[r * 128 + c4] = *(const float4*)&vbase[(size_t)r * KVD + c4];
        }
        __syncthreads();

        ull s2[4][2] = {{0ull,0ull},{0ull,0ull},{0ull,0ull},{0ull,0ull}};
#pragma unroll 8
        for (int d = 0; d < 128; ++d) {
            const float* kr = &Kt[d * QK_STRIDE];
            ull b01 = *(const ull*)(kr + tx4);
            ull b23 = *(const ull*)(kr + tx4 + 2);
            float4 a = *(const float4*)&Qt[d * QK_STRIDE + ty4];
            float avv[4] = {a.x, a.y, a.z, a.w};
#pragma unroll
            for (int i = 0; i < 4; ++i) {
                ull aa = pk2(avv[i], avv[i]);
                s2[i][0] = f2fma(aa, b01, s2[i][0]);
                s2[i][1] = f2fma(aa, b23, s2[i][1]);
            }
        }
        float s[4][4];
#pragma unroll
        for (int i = 0; i < 4; ++i) {
            up2(s2[i][0], s[i][0], s[i][1]);
            up2(s2[i][1], s[i][2], s[i][3]);
        }

        if (kb == qb) {
#pragma unroll
            for (int i = 0; i < 4; ++i)
#pragma unroll
                for (int j = 0; j < 4; ++j)
                    if (tx4 + j > ty4 + i) s[i][j] = -1e30f;
        }

        float p[4][4], rsum[4], alpha[4];
#pragma unroll
        for (int i = 0; i < 4; ++i) {
            float mx = fmaxf(fmaxf(s[i][0], s[i][1]), fmaxf(s[i][2], s[i][3]));
#pragma unroll
            for (int off = 8; off >= 1; off >>= 1)
                mx = fmaxf(mx, __shfl_xor_sync(0xffffffffu, mx, off));
            float mn = fmaxf(m_i[i], mx);
            alpha[i] = __expf(m_i[i] - mn);
            m_i[i] = mn;
            float rs = 0.0f;
#pragma unroll
            for (int j = 0; j < 4; ++j) {
                p[i][j] = __expf(s[i][j] - mn);
                rs += p[i][j];
            }
#pragma unroll
            for (int off = 8; off >= 1; off >>= 1)
                rs += __shfl_xor_sync(0xffffffffu, rs, off);
            rsum[i] = rs;
        }
#pragma unroll
        for (int i = 0; i < 4; ++i) {
            l_i[i] = l_i[i] * alpha[i] + rsum[i];
            ull al2 = pk2(alpha[i], alpha[i]);
#pragma unroll
            for (int j = 0; j < 4; ++j) o2[i][j] = f2mul(o2[i][j], al2);
#pragma unroll
            for (int j = 0; j < 4; ++j) Ps[(ty4 + i) * PS_STRIDE + tx4 + j] = p[i][j];
        }
        __syncthreads();

#pragma unroll 4
        for (int j = 0; j < FA_BN; ++j) {
            const float* vr = &Vs[j * 128 + tx8];
            ull v0 = *(const ull*)(vr + 0);
            ull v1 = *(const ull*)(vr + 2);
            ull v2 = *(const ull*)(vr + 4);
            ull v3 = *(const ull*)(vr + 6);
#pragma unroll
            for (int i = 0; i < 4; ++i) {
                float pv = Ps[(ty4 + i) * PS_STRIDE + j];
                ull p2 = pk2(pv, pv);
                o2[i][0] = f2fma(p2, v0, o2[i][0]);
                o2[i][1] = f2fma(p2, v1, o2[i][1]);
                o2[i][2] = f2fma(p2, v2, o2[i][2]);
                o2[i][3] = f2fma(p2, v3, o2[i][3]);
            }
        }
    }

    // ---- epilogue: normalize + bf16 hi/lo split store ----
#pragma unroll
    for (int i = 0; i < 4; ++i) {
        float inv = 1.0f / l_i[i];
        float o[8];
        up2(o2[i][0], o[0], o[1]); up2(o2[i][1], o[2], o[3]);
        up2(o2[i][2], o[4], o[5]); up2(o2[i][3], o[6], o[7]);
        __nv_bfloat16 hb[8], lb[8];
#pragma unroll
        for (int jj = 0; jj < 8; ++jj) {
            float vv = o[jj] * inv;
            hb[jj] = __float2bfloat16(vv);
            lb[jj] = __float2bfloat16(vv - __bfloat162float(hb[jj]));
        }
        size_t off = (size_t)(b * SEQ + qb * FA_BM + ty4 + i) * DMODEL + h * HEADD + tx8;
        *(uint4*)&oh[off] = *(const uint4*)hb;
        *(uint4*)&ol[off] = *(const uint4*)lb;
    }
}

// =================================================================================
// Host launcher
// =================================================================================
extern "C" void kernel_launch(void* const* d_in, const int* in_sizes, int n_in,
                              void* d_out, int out_size)
{
    const float* x    = (const float*)d_in[0];
    const float* wq   = (const float*)d_in[1];
    const float* wk   = (const float*)d_in[2];
    const float* wv   = (const float*)d_in[3];
    const float* wo   = (const float*)d_in[4];
    const float* fcos = (const float*)d_in[5];
    const float* fsin = (const float*)d_in[6];
    float* outp = (float*)d_out;

    float *gq, *gk, *gv;
    cudaGetSymbolAddress((void**)&gq, g_q);
    cudaGetSymbolAddress((void**)&gk, g_k);
    cudaGetSymbolAddress((void**)&gv, g_v);

    __nv_bfloat16 *xh, *xl, *ah, *al, *wqkvh, *wqkvl, *woh, *wol;
    cudaGetSymbolAddress((void**)&xh, s_xh);       cudaGetSymbolAddress((void**)&xl, s_xl);
    cudaGetSymbolAddress((void**)&ah, s_ah);       cudaGetSymbolAddress((void**)&al, s_al);
    cudaGetSymbolAddress((void**)&wqkvh, s_wqkvh); cudaGetSymbolAddress((void**)&wqkvl, s_wqkvl);
    cudaGetSymbolAddress((void**)&woh, s_woh);     cudaGetSymbolAddress((void**)&wol, s_wol);

    cudaFuncSetAttribute(flash_kernel,
                         cudaFuncAttributeMaxDynamicSharedMemorySize, FA_SMEM_BYTES);
    cudaFuncSetAttribute(gemm_bf16x3_fused,
                         cudaFuncAttributeMaxDynamicSharedMemorySize, GEMM_SMEM);

    // ---- operand conversions (weights packed [q | k | v] along N) ----
    {
        int n = NROWS * DMODEL;
        convert_split2<<<(n + 255) / 256, 256>>>(x, xh, xl, n);
    }
    transpose_split2<<<dim3(DMODEL / 32, DMODEL / 32), dim3(32, 8)>>>(
        wq, wqkvh, wqkvl, DMODEL, DMODEL);
    transpose_split2<<<dim3(KVD / 32, DMODEL / 32), dim3(32, 8)>>>(
        wk, wqkvh + (size_t)DMODEL * DMODEL, wqkvl + (size_t)DMODEL * DMODEL, DMODEL, KVD);
    transpose_split2<<<dim3(KVD / 32, DMODEL / 32), dim3(32, 8)>>>(
        wv, wqkvh + (size_t)(DMODEL + KVD) * DMODEL, wqkvl + (size_t)(DMODEL + KVD) * DMODEL,
        DMODEL, KVD);
    transpose_split2<<<dim3(DMODEL / 32, DMODEL / 32), dim3(32, 8)>>>(
        wo, woh, wol, DMODEL, DMODEL);

    // ---- Fused QKV projection (one GEMM, N=6144) with fused RoPE on q/k ----
    gemm_bf16x3_fused<<<dim3(NQKV / 128, NROWS / 128), 128, GEMM_SMEM>>>(
        xh, xl, wqkvh, wqkvl, gq, gk, gv, fcos, fsin, DMODEL, 1);

    // ---- Flash attention (writes bf16 hi/lo split directly) ----
    flash_kernel<<<dim3(SEQ / FA_BM, NHEADS, BATCH), 256, FA_SMEM_BYTES>>>(
        gq, gk, gv, ah, al);

    // ---- O projection -> d_out (no rope; all tiles region 0) ----
    gemm_bf16x3_fused<<<dim3(DMODEL / 128, NROWS / 128), 128, GEMM_SMEM>>>(
        ah, al, woh, wol, outp, outp, outp, fcos, fsin, DMODEL, 0);
}